// round 4
// baseline (speedup 1.0000x reference)
#include <cuda_runtime.h>

#define EPS 1e-6f

static const int MAX_N = 50000;
static const int CH    = 128;   // channels in/out

// Scratch (allocation-free rule: __device__ globals)
__device__ int   g_src_deg[MAX_N];
__device__ int   g_dst_deg[MAX_N];
__device__ float g_src_inv[MAX_N];
__device__ float g_dst_inv[MAX_N];
__device__ __align__(16) float g_agg[(size_t)MAX_N * CH];
__device__ int   g_idx64;   // 1 = edge_index is int64, 0 = int32

// ---------------------------------------------------------------------------
// helpers
// ---------------------------------------------------------------------------
__device__ __forceinline__ int edge_at(const void* ei, int pos, int mode64) {
    if (mode64) return (int)((const long long*)ei)[pos];
    return ((const int*)ei)[pos];
}

__device__ __forceinline__ unsigned long long pack2(float lo, float hi) {
    unsigned long long d;
    asm("mov.b64 %0, {%1, %2};" : "=l"(d) : "f"(lo), "f"(hi));
    return d;
}
__device__ __forceinline__ void unpack2(unsigned long long v, float& lo, float& hi) {
    asm("mov.b64 {%0, %1}, %2;" : "=f"(lo), "=f"(hi) : "l"(v));
}
__device__ __forceinline__ unsigned long long fma2(unsigned long long a,
                                                   unsigned long long b,
                                                   unsigned long long c) {
    unsigned long long d;
    asm("fma.rn.f32x2 %0, %1, %2, %3;" : "=l"(d) : "l"(a), "l"(b), "l"(c));
    return d;
}

// ---------------------------------------------------------------------------
// 0) detect edge_index dtype: sample first 256 values as int64; any value
//    outside [0, N) => buffer is really int32. Deterministic per input.
// ---------------------------------------------------------------------------
__global__ void detect_kernel(const long long* __restrict__ ei, int twoE, int N) {
    if (threadIdx.x == 0 && blockIdx.x == 0) {
        int n = twoE < 256 ? twoE : 256;
        int mode = 1;
        for (int i = 0; i < n; i++) {
            long long v = ei[i];
            if (v < 0 || v >= (long long)N) { mode = 0; break; }
        }
        g_idx64 = mode;
    }
}

// ---------------------------------------------------------------------------
// 1) zero agg + degree counters
// ---------------------------------------------------------------------------
__global__ void zero_kernel(int n_nodes) {
    int tid    = blockIdx.x * blockDim.x + threadIdx.x;
    int stride = gridDim.x * blockDim.x;
    float4* agg4 = reinterpret_cast<float4*>(g_agg);
    int n4 = n_nodes * (CH / 4);
    for (int i = tid; i < n4; i += stride) agg4[i] = make_float4(0.f, 0.f, 0.f, 0.f);
    for (int i = tid; i < n_nodes; i += stride) { g_src_deg[i] = 0; g_dst_deg[i] = 0; }
}

// ---------------------------------------------------------------------------
// 2) degree histogram (bincount over src and dst)
// ---------------------------------------------------------------------------
__global__ void degree_kernel(const void* __restrict__ ei, int E) {
    int e = blockIdx.x * blockDim.x + threadIdx.x;
    if (e >= E) return;
    int m = g_idx64;
    int s = edge_at(ei, e, m);
    int d = edge_at(ei, E + e, m);
    atomicAdd(&g_src_deg[s], 1);
    atomicAdd(&g_dst_deg[d], 1);
}

// ---------------------------------------------------------------------------
// 3) per-node rsqrt(deg + eps)
// ---------------------------------------------------------------------------
__global__ void inv_kernel(int N) {
    int i = blockIdx.x * blockDim.x + threadIdx.x;
    if (i >= N) return;
    g_src_inv[i] = rsqrtf((float)g_src_deg[i] + EPS);
    g_dst_inv[i] = rsqrtf((float)g_dst_deg[i] + EPS);
}

// ---------------------------------------------------------------------------
// 4) scatter-aggregate: one warp per edge.
//    lane k handles float4 #k of the 128-channel row (32 float4 = 512B/warp).
//    agg[dst] += x[src] * norm(e) via vectorized red.global.add.v4.f32
// ---------------------------------------------------------------------------
__global__ void scatter_kernel(const void* __restrict__ ei,
                               const float4* __restrict__ x4, int E) {
    int lane  = threadIdx.x & 31;
    int warp  = (blockIdx.x * blockDim.x + threadIdx.x) >> 5;
    int nwarp = (gridDim.x * blockDim.x) >> 5;
    int m = g_idx64;
    for (int e = warp; e < E; e += nwarp) {
        int s = 0, d = 0;
        float nrm = 0.f;
        if (lane == 0) {
            s   = edge_at(ei, e, m);
            d   = edge_at(ei, E + e, m);
            nrm = g_src_inv[s] * g_dst_inv[d];
        }
        s   = __shfl_sync(0xffffffffu, s, 0);
        d   = __shfl_sync(0xffffffffu, d, 0);
        nrm = __shfl_sync(0xffffffffu, nrm, 0);

        float4 v = __ldg(&x4[(size_t)s * (CH / 4) + lane]);
        v.x *= nrm; v.y *= nrm; v.z *= nrm; v.w *= nrm;

        float* p = g_agg + ((size_t)d * CH + (lane << 2));
        asm volatile("red.global.add.v4.f32 [%0], {%1,%2,%3,%4};"
                     :: "l"(p), "f"(v.x), "f"(v.y), "f"(v.z), "f"(v.w)
                     : "memory");
    }
}

// ---------------------------------------------------------------------------
// 5) out = agg @ W + bias
//    W (128x128 fp32 = 64KB) staged in dynamic shared memory.
//    Each warp computes 4 rows at once (amortizes the W smem reads 4x);
//    lane owns 4 consecutive output channels; packed fma.rn.f32x2 doubles
//    the fp32 FMA rate on sm_103a.
// ---------------------------------------------------------------------------
__global__ void gemm_kernel(const float4* __restrict__ W4,
                            const float4* __restrict__ bias4,
                            float4* __restrict__ out4, int N) {
    extern __shared__ float4 Ws[];   // [128 k][32 float4-of-channels] = 64KB
    int tid = threadIdx.x;
    for (int i = tid; i < CH * (CH / 4); i += blockDim.x) Ws[i] = W4[i];
    __syncthreads();

    int lane = tid & 31;
    int warp = tid >> 5;
    int wpb  = blockDim.x >> 5;
    float4 b = __ldg(&bias4[lane]);
    unsigned long long b01 = pack2(b.x, b.y);
    unsigned long long b23 = pack2(b.z, b.w);

    for (int row0 = (blockIdx.x * wpb + warp) * 4; row0 < N;
         row0 += gridDim.x * wpb * 4) {
        // preload A: 4 rows, 4 k-chunks each (k = j*32 + lane)
        float ar[4][4];
        #pragma unroll
        for (int r = 0; r < 4; r++) {
            int row = row0 + r;
            const float* a = g_agg + (size_t)row * CH;
            bool ok = row < N;
            #pragma unroll
            for (int j = 0; j < 4; j++)
                ar[r][j] = ok ? a[j * 32 + lane] : 0.f;
        }

        unsigned long long acc01[4], acc23[4];
        #pragma unroll
        for (int r = 0; r < 4; r++) { acc01[r] = b01; acc23[r] = b23; }

        #pragma unroll
        for (int j = 0; j < 4; j++) {
            #pragma unroll
            for (int cc = 0; cc < 32; cc++) {
                int k = j * 32 + cc;
                float4 w = Ws[k * 32 + lane];
                unsigned long long w01 = pack2(w.x, w.y);
                unsigned long long w23 = pack2(w.z, w.w);
                #pragma unroll
                for (int r = 0; r < 4; r++) {
                    float av = __shfl_sync(0xffffffffu, ar[r][j], cc);
                    unsigned long long av2 = pack2(av, av);
                    acc01[r] = fma2(av2, w01, acc01[r]);
                    acc23[r] = fma2(av2, w23, acc23[r]);
                }
            }
        }

        #pragma unroll
        for (int r = 0; r < 4; r++) {
            int row = row0 + r;
            if (row < N) {
                float4 o;
                unpack2(acc01[r], o.x, o.y);
                unpack2(acc23[r], o.z, o.w);
                out4[(size_t)row * (CH / 4) + lane] = o;
            }
        }
    }
}

// ---------------------------------------------------------------------------
// Launch
// inputs (metadata order): x [N,128] f32, edge_index [2,E] (int32 or int64),
//                          weight [128,128] f32, bias [128] f32
// output: [N,128] f32
// ---------------------------------------------------------------------------
extern "C" void kernel_launch(void* const* d_in, const int* in_sizes, int n_in,
                              void* d_out, int out_size) {
    const float* x    = (const float*)d_in[0];
    const void*  ei   = d_in[1];
    const float* W    = (const float*)d_in[2];
    const float* bias = (const float*)d_in[3];
    float*       out  = (float*)d_out;

    int N = in_sizes[0] / CH;
    int E = in_sizes[1] / 2;

    detect_kernel<<<1, 32>>>((const long long*)ei, 2 * E, N);
    zero_kernel<<<1024, 256>>>(N);
    degree_kernel<<<(E + 255) / 256, 256>>>(ei, E);
    inv_kernel<<<(N + 255) / 256, 256>>>(N);
    scatter_kernel<<<3200, 256>>>(ei, (const float4*)x, E);

    cudaFuncSetAttribute(gemm_kernel,
                         cudaFuncAttributeMaxDynamicSharedMemorySize, 65536);
    gemm_kernel<<<444, 256, 65536>>>((const float4*)W, (const float4*)bias,
                                     (float4*)out, N);
}

// round 6
// speedup vs baseline: 1.0434x; 1.0434x over previous
#include <cuda_runtime.h>

#define EPS 1e-6f

static const int MAX_N = 50000;
static const int MAX_E = 800000;
static const int CH    = 128;

// Scratch (allocation-free rule: __device__ globals)
__device__ int   g_src_deg[MAX_N];
__device__ int   g_dst_deg[MAX_N];
__device__ float g_src_inv[MAX_N];
__device__ float g_dst_inv[MAX_N];
__device__ int   g_cursor[MAX_N];        // bin cursors (post-fill: bin end)
__device__ int   g_sorted_src[MAX_E];    // src ids grouped by dst
__device__ __align__(16) float g_y[(size_t)MAX_N * CH];   // y = x @ W
__device__ int   g_idx64;                // 1 = edge_index int64, 0 = int32

// ---------------------------------------------------------------------------
// helpers
// ---------------------------------------------------------------------------
__device__ __forceinline__ int edge_at(const void* ei, int pos, int mode64) {
    if (mode64) return (int)((const long long*)ei)[pos];
    return ((const int*)ei)[pos];
}

__device__ __forceinline__ unsigned long long pack2(float lo, float hi) {
    unsigned long long d;
    asm("mov.b64 %0, {%1, %2};" : "=l"(d) : "f"(lo), "f"(hi));
    return d;
}
__device__ __forceinline__ void unpack2(unsigned long long v, float& lo, float& hi) {
    asm("mov.b64 {%0, %1}, %2;" : "=f"(lo), "=f"(hi) : "l"(v));
}
__device__ __forceinline__ unsigned long long fma2(unsigned long long a,
                                                   unsigned long long b,
                                                   unsigned long long c) {
    unsigned long long d;
    asm("fma.rn.f32x2 %0, %1, %2, %3;" : "=l"(d) : "l"(a), "l"(b), "l"(c));
    return d;
}

// ---------------------------------------------------------------------------
// 0) dtype detect (int64 vs int32 edge_index) — deterministic per input
// ---------------------------------------------------------------------------
__global__ void detect_kernel(const long long* __restrict__ ei, int twoE, int N) {
    if (threadIdx.x == 0 && blockIdx.x == 0) {
        int n = twoE < 256 ? twoE : 256;
        int mode = 1;
        for (int i = 0; i < n; i++) {
            long long v = ei[i];
            if (v < 0 || v >= (long long)N) { mode = 0; break; }
        }
        g_idx64 = mode;
    }
}

// ---------------------------------------------------------------------------
// 1) zero degree counters
// ---------------------------------------------------------------------------
__global__ void zero_deg_kernel(int N) {
    int i = blockIdx.x * blockDim.x + threadIdx.x;
    if (i < N) { g_src_deg[i] = 0; g_dst_deg[i] = 0; }
}

// ---------------------------------------------------------------------------
// 2) degree histogram
// ---------------------------------------------------------------------------
__global__ void degree_kernel(const void* __restrict__ ei, int E) {
    int e = blockIdx.x * blockDim.x + threadIdx.x;
    if (e >= E) return;
    int m = g_idx64;
    atomicAdd(&g_src_deg[edge_at(ei, e, m)], 1);
    atomicAdd(&g_dst_deg[edge_at(ei, E + e, m)], 1);
}

// ---------------------------------------------------------------------------
// 3) per-node rsqrt(deg + eps)
// ---------------------------------------------------------------------------
__global__ void inv_kernel(int N) {
    int i = blockIdx.x * blockDim.x + threadIdx.x;
    if (i >= N) return;
    g_src_inv[i] = rsqrtf((float)g_src_deg[i] + EPS);
    g_dst_inv[i] = rsqrtf((float)g_dst_deg[i] + EPS);
}

// ---------------------------------------------------------------------------
// 4) exclusive scan of dst_deg -> bin cursors (single block, 1024 threads)
// ---------------------------------------------------------------------------
__global__ void scan_kernel(int N) {
    __shared__ int sums[1024];
    int t = threadIdx.x;
    int C = (N + 1023) / 1024;
    int beg = t * C;
    int end = beg + C < N ? beg + C : N;

    int s = 0;
    for (int i = beg; i < end; i++) s += g_dst_deg[i];
    sums[t] = s;
    __syncthreads();
    // Hillis-Steele inclusive scan
    for (int off = 1; off < 1024; off <<= 1) {
        int u = (t >= off) ? sums[t - off] : 0;
        __syncthreads();
        sums[t] += u;
        __syncthreads();
    }
    int run = sums[t] - s;   // exclusive prefix of this thread's chunk
    for (int i = beg; i < end; i++) {
        g_cursor[i] = run;
        run += g_dst_deg[i];
    }
}

// ---------------------------------------------------------------------------
// 5) counting-sort fill: group src ids by dst
//    (after this, g_cursor[d] == end of bin d; begin = end - dst_deg[d])
// ---------------------------------------------------------------------------
__global__ void fill_kernel(const void* __restrict__ ei, int E) {
    int e = blockIdx.x * blockDim.x + threadIdx.x;
    if (e >= E) return;
    int m = g_idx64;
    int s = edge_at(ei, e, m);
    int d = edge_at(ei, E + e, m);
    int pos = atomicAdd(&g_cursor[d], 1);
    g_sorted_src[pos] = s;
}

// ---------------------------------------------------------------------------
// 6) y = x @ W  (no bias; bias folded into aggregate).
//    W in 64KB smem; each warp computes 4 rows; packed fma.rn.f32x2.
// ---------------------------------------------------------------------------
__global__ void gemm_kernel(const float4* __restrict__ X4,
                            const float4* __restrict__ W4, int N) {
    extern __shared__ float4 Ws[];   // [128 k][32 float4-of-channels]
    int tid = threadIdx.x;
    for (int i = tid; i < CH * (CH / 4); i += blockDim.x) Ws[i] = W4[i];
    __syncthreads();

    int lane = tid & 31;
    int warp = tid >> 5;
    int wpb  = blockDim.x >> 5;
    float4* Y4 = reinterpret_cast<float4*>(g_y);

    for (int row0 = (blockIdx.x * wpb + warp) * 4; row0 < N;
         row0 += gridDim.x * wpb * 4) {
        float ar[4][4];
        #pragma unroll
        for (int r = 0; r < 4; r++) {
            int row = row0 + r;
            bool ok = row < N;
            const float* a = reinterpret_cast<const float*>(X4) + (size_t)row * CH;
            #pragma unroll
            for (int j = 0; j < 4; j++)
                ar[r][j] = ok ? __ldg(&a[j * 32 + lane]) : 0.f;
        }

        unsigned long long acc01[4] = {0, 0, 0, 0}, acc23[4] = {0, 0, 0, 0};

        #pragma unroll
        for (int j = 0; j < 4; j++) {
            #pragma unroll
            for (int cc = 0; cc < 32; cc++) {
                float4 w = Ws[(j * 32 + cc) * 32 + lane];
                unsigned long long w01 = pack2(w.x, w.y);
                unsigned long long w23 = pack2(w.z, w.w);
                #pragma unroll
                for (int r = 0; r < 4; r++) {
                    float av = __shfl_sync(0xffffffffu, ar[r][j], cc);
                    unsigned long long av2 = pack2(av, av);
                    acc01[r] = fma2(av2, w01, acc01[r]);
                    acc23[r] = fma2(av2, w23, acc23[r]);
                }
            }
        }

        #pragma unroll
        for (int r = 0; r < 4; r++) {
            int row = row0 + r;
            if (row < N) {
                float4 o;
                unpack2(acc01[r], o.x, o.y);
                unpack2(acc23[r], o.z, o.w);
                Y4[(size_t)row * (CH / 4) + lane] = o;
            }
        }
    }
}

// ---------------------------------------------------------------------------
// 7) aggregate: one warp per dst node.
//    out[d] = dst_inv[d] * sum_{e in bin(d)} src_inv[s]*y[s]  + bias
//    Register accumulation, single 512B store per node. Edge loop unrolled x2
//    for gather MLP.
// ---------------------------------------------------------------------------
__global__ void aggregate_kernel(const float4* __restrict__ bias4,
                                 float4* __restrict__ out4, int N) {
    int lane  = threadIdx.x & 31;
    int warp  = (blockIdx.x * blockDim.x + threadIdx.x) >> 5;
    int nwarp = (gridDim.x * blockDim.x) >> 5;
    const float4* Y4 = reinterpret_cast<const float4*>(g_y);
    float4 b = __ldg(&bias4[lane]);

    for (int node = warp; node < N; node += nwarp) {
        int end = g_cursor[node];
        int beg = end - g_dst_deg[node];

        float4 acc = make_float4(0.f, 0.f, 0.f, 0.f);
        int i = beg;
        for (; i + 1 < end; i += 2) {
            int s0 = g_sorted_src[i];
            int s1 = g_sorted_src[i + 1];
            float f0 = g_src_inv[s0];
            float f1 = g_src_inv[s1];
            float4 v0 = __ldg(&Y4[(size_t)s0 * (CH / 4) + lane]);
            float4 v1 = __ldg(&Y4[(size_t)s1 * (CH / 4) + lane]);
            acc.x += f0 * v0.x + f1 * v1.x;
            acc.y += f0 * v0.y + f1 * v1.y;
            acc.z += f0 * v0.z + f1 * v1.z;
            acc.w += f0 * v0.w + f1 * v1.w;
        }
        if (i < end) {
            int s0 = g_sorted_src[i];
            float f0 = g_src_inv[s0];
            float4 v0 = __ldg(&Y4[(size_t)s0 * (CH / 4) + lane]);
            acc.x += f0 * v0.x;
            acc.y += f0 * v0.y;
            acc.z += f0 * v0.z;
            acc.w += f0 * v0.w;
        }

        float di = g_dst_inv[node];
        float4 o;
        o.x = acc.x * di + b.x;
        o.y = acc.y * di + b.y;
        o.z = acc.z * di + b.z;
        o.w = acc.w * di + b.w;
        out4[(size_t)node * (CH / 4) + lane] = o;
    }
}

// ---------------------------------------------------------------------------
// Launch
// inputs: x [N,128] f32, edge_index [2,E] (i32/i64), weight [128,128] f32,
//         bias [128] f32;  output: [N,128] f32
// ---------------------------------------------------------------------------
extern "C" void kernel_launch(void* const* d_in, const int* in_sizes, int n_in,
                              void* d_out, int out_size) {
    const float* x    = (const float*)d_in[0];
    const void*  ei   = d_in[1];
    const float* W    = (const float*)d_in[2];
    const float* bias = (const float*)d_in[3];
    float*       out  = (float*)d_out;

    int N = in_sizes[0] / CH;
    int E = in_sizes[1] / 2;

    detect_kernel<<<1, 32>>>((const long long*)ei, 2 * E, N);
    zero_deg_kernel<<<(N + 255) / 256, 256>>>(N);
    degree_kernel<<<(E + 255) / 256, 256>>>(ei, E);
    inv_kernel<<<(N + 255) / 256, 256>>>(N);
    scan_kernel<<<1, 1024>>>(N);
    fill_kernel<<<(E + 255) / 256, 256>>>(ei, E);

    cudaFuncSetAttribute(gemm_kernel,
                         cudaFuncAttributeMaxDynamicSharedMemorySize, 65536);
    gemm_kernel<<<444, 256, 65536>>>((const float4*)x, (const float4*)W, N);

    aggregate_kernel<<<2048, 256>>>((const float4*)bias, (float4*)out, N);
}